// round 2
// baseline (speedup 1.0000x reference)
#include <cuda_runtime.h>
#include <math.h>

// Problem constants (fixed by the dataset)
#define MM        16
#define TE        64     // edges per block
#define NTHREADS  256
#define NGROUPS   112    // 112 groups of 16 columns = 1792
#define NCHUNK    28     // 112 groups / 4 groups-per-chunk

// Scalar constants
#define C_A0      0.17677669529663687f   // 1/sqrt(2*M)
#define C_A0I3    0.10206207261596575f   // A0/sqrt(3)
#define C_A1      0.14433756729740643f   // 1/sqrt(3*M)
#define C_A1I2    0.10206207261596577f   // A1/sqrt(2)

// ---------------- device scratch (no allocations allowed) ----------------
__device__ float g_acc[10000 * 80];          // per-node message accumulator
__device__ float g_cnt[10000];               // per-node edge count
__device__ float g_W2r[NGROUPS * 128 * 16];  // column-reordered We2: [chunk][h][4*16]
__device__ float g_be2r[1792];               // reordered be2: [g][m]

// ---------------- zero accumulators ----------------
__global__ void zero_acc_kernel() {
    int idx = blockIdx.x * blockDim.x + threadIdx.x;
    if (idx < 10000 * 80) g_acc[idx] = 0.f;
    if (idx < 10000)      g_cnt[idx] = 0.f;
}

// ---------------- reorder We2/be2 into group-major layout ----------------
// group g (0..111): [0,32) ss (o=g), [32,64) vv0, [64,80) sv, [80,96) vs, [96,112) vv1
// reordered index: pos = (g/4)*8192 + h*64 + (g%4)*16 + m   (matches smem chunk image)
__device__ __forceinline__ int orig_k(int g, int m) {
    if (g < 32)  return         m * 32 + g;
    if (g < 64)  return  512 +  m * 32 + (g - 32);
    if (g < 80)  return 1024 +  m * 16 + (g - 64);
    if (g < 96)  return 1280 +  m * 16 + (g - 80);
    return              1536 +  m * 16 + (g - 96);
}

__global__ void prep_kernel(const float* __restrict__ We2, const float* __restrict__ be2) {
    int idx = blockIdx.x * blockDim.x + threadIdx.x;
    if (idx >= NGROUPS * 128 * 16) return;
    int g = idx >> 11;          // /2048
    int r = idx & 2047;
    int h = r >> 4;
    int m = r & 15;
    int k = orig_k(g, m);
    int pos = (g >> 2) * 8192 + h * 64 + (g & 3) * 16 + m;
    g_W2r[pos] = We2[h * 1792 + k];
    if (h == 0) g_be2r[g * 16 + m] = be2[k];
}

// ---------------- fused main kernel ----------------
// Per block: TE=64 edges.
//  Phase 0: load ea/x_src/sh tiles, compute h = relu(ea@We1+be1) into smem (transposed).
//  Chunk loop (28): load 64 reordered We2 columns, each thread (e, group) computes
//  16 dot products over h (the w values), contracts with per-edge equivariant
//  coefficients, and atomically scatters into the destination-node accumulator.
//
// shared layout (floats):
//  xs_s  [64*69]   @ 0      (x_src 64 + sh 4, padded stride 69 -> conflict-free)
//  dst_s [64]      @ 4416
//  h_s   [128*64]  @ 4480   (h_s[h*64+e], conflict-free across warp-e)
//  w2_s  [8192]    @ 12672  (union with phase-0 ea_s/We1_s/be1_s)
__global__ __launch_bounds__(NTHREADS, 2)
void conv_main_kernel(const int*   __restrict__ dst,
                      const float* __restrict__ x_src,
                      const float* __restrict__ sh,
                      const float* __restrict__ edge_attr,
                      const float* __restrict__ We1,
                      const float* __restrict__ be1,
                      int E)
{
    extern __shared__ float sm[];
    float* xs_s  = sm;                  // 64*69 = 4416
    int*   dst_s = (int*)(sm + 4416);   // 64
    float* h_s   = sm + 4480;           // 8192
    float* w2_s  = sm + 12672;          // 8192
    // phase-0 union inside w2_s region:
    float* ea_s  = w2_s;                // 64*33 = 2112
    float* We1_s = w2_s + 2112;         // 4096
    float* be1_s = w2_s + 6208;         // 128

    const int tid = threadIdx.x;
    const int e0  = blockIdx.x * TE;

    // ---- phase 0: loads ----
    for (int idx = tid; idx < 64 * 32; idx += NTHREADS) {
        int e = idx >> 5, d = idx & 31;
        int eg = e0 + e;
        ea_s[e * 33 + d] = (eg < E) ? edge_attr[eg * 32 + d] : 0.f;
    }
    for (int idx = tid; idx < 4096; idx += NTHREADS) We1_s[idx] = We1[idx];
    if (tid < 128) be1_s[tid] = be1[tid];
    for (int idx = tid; idx < 64 * 64; idx += NTHREADS) {
        int e = idx >> 6, j = idx & 63;
        int eg = e0 + e;
        xs_s[e * 69 + j] = (eg < E) ? x_src[eg * 64 + j] : 0.f;
    }
    {   // sh: 64 edges * 4
        int e = tid >> 2, j = tid & 3;
        int eg = e0 + e;
        xs_s[e * 69 + 64 + j] = (eg < E) ? sh[eg * 4 + j] : 0.f;
    }
    if (tid < 64) {
        int eg = e0 + tid;
        int dv = (eg < E) ? dst[eg] : 0;
        dst_s[tid] = dv;
        if (eg < E) atomicAdd(&g_cnt[dv], 1.f);   // each edge counted exactly once
    }
    __syncthreads();

    // ---- phase 0b: h = relu(ea @ We1 + be1), stored transposed ----
    for (int idx = tid; idx < 8192; idx += NTHREADS) {
        int e = idx & 63, h = idx >> 6;
        float s = be1_s[h];
        const float* ea = &ea_s[e * 33];
        #pragma unroll
        for (int d = 0; d < 32; d++) s = fmaf(ea[d], We1_s[d * 128 + h], s);
        h_s[h * 64 + e] = fmaxf(s, 0.f);
    }
    __syncthreads();

    // ---- chunk loop ----
    const int e  = tid & 63;
    const int jg = tid >> 6;             // 0..3, group within chunk
    const int eg = e0 + e;
    const float* xs = &xs_s[e * 69];
    const float  s2  = xs[64];
    const float  v2x = xs[65], v2y = xs[66], v2z = xs[67];
    float* nacc = g_acc + dst_s[e] * 80;
    const float* hp = h_s + e;           // h_s[h*64 + e]
    const float* wp = w2_s + jg * 16;

    for (int c = 0; c < NCHUNK; c++) {
        for (int idx = tid; idx < 8192; idx += NTHREADS)
            w2_s[idx] = g_W2r[c * 8192 + idx];
        __syncthreads();

        float acc[16];
        #pragma unroll
        for (int m = 0; m < 16; m++) acc[m] = 0.f;

        #pragma unroll 4
        for (int h = 0; h < 128; h++) {
            float hv = hp[h * 64];
            const float4* w4 = (const float4*)(wp + h * 64);
            float4 a = w4[0], b = w4[1], cc = w4[2], dd = w4[3];
            acc[0]  = fmaf(hv, a.x,  acc[0]);  acc[1]  = fmaf(hv, a.y,  acc[1]);
            acc[2]  = fmaf(hv, a.z,  acc[2]);  acc[3]  = fmaf(hv, a.w,  acc[3]);
            acc[4]  = fmaf(hv, b.x,  acc[4]);  acc[5]  = fmaf(hv, b.y,  acc[5]);
            acc[6]  = fmaf(hv, b.z,  acc[6]);  acc[7]  = fmaf(hv, b.w,  acc[7]);
            acc[8]  = fmaf(hv, cc.x, acc[8]);  acc[9]  = fmaf(hv, cc.y, acc[9]);
            acc[10] = fmaf(hv, cc.z, acc[10]); acc[11] = fmaf(hv, cc.w, acc[11]);
            acc[12] = fmaf(hv, dd.x, acc[12]); acc[13] = fmaf(hv, dd.y, acc[13]);
            acc[14] = fmaf(hv, dd.z, acc[14]); acc[15] = fmaf(hv, dd.w, acc[15]);
        }

        if (eg < E) {
            const int g = c * 4 + jg;
            const float* bp = &g_be2r[g * 16];
            float wk[16];
            #pragma unroll
            for (int m = 0; m < 16; m++) wk[m] = acc[m] + __ldg(&bp[m]);

            if (g < 32) {                     // ss: coeff = A0*s2*s1[m]
                float t = 0.f;
                #pragma unroll
                for (int m = 0; m < 16; m++) t = fmaf(xs[m], wk[m], t);
                atomicAdd(&nacc[g], C_A0 * s2 * t);
            } else if (g < 64) {              // vv0: coeff = A0/sqrt3 * (v1.v2)[m]
                float t = 0.f;
                #pragma unroll
                for (int m = 0; m < 16; m++) {
                    const float* v1 = &xs[16 + 3 * m];
                    float dotv = v1[0] * v2x + v1[1] * v2y + v1[2] * v2z;
                    t = fmaf(dotv, wk[m], t);
                }
                atomicAdd(&nacc[g - 32], C_A0I3 * t);
            } else if (g < 80) {              // sv: A1 * s1[m] * v2[c]
                float t = 0.f;
                #pragma unroll
                for (int m = 0; m < 16; m++) t = fmaf(xs[m], wk[m], t);
                float a = C_A1 * t;
                int o = g - 64;
                atomicAdd(&nacc[32 + o * 3 + 0], a * v2x);
                atomicAdd(&nacc[32 + o * 3 + 1], a * v2y);
                atomicAdd(&nacc[32 + o * 3 + 2], a * v2z);
            } else if (g < 96) {              // vs: A1 * s2 * v1[m,c]
                float tx = 0.f, ty = 0.f, tz = 0.f;
                #pragma unroll
                for (int m = 0; m < 16; m++) {
                    const float* v1 = &xs[16 + 3 * m];
                    tx = fmaf(v1[0], wk[m], tx);
                    ty = fmaf(v1[1], wk[m], ty);
                    tz = fmaf(v1[2], wk[m], tz);
                }
                float a = C_A1 * s2;
                int o = g - 80;
                atomicAdd(&nacc[32 + o * 3 + 0], a * tx);
                atomicAdd(&nacc[32 + o * 3 + 1], a * ty);
                atomicAdd(&nacc[32 + o * 3 + 2], a * tz);
            } else {                          // vv1: A1/sqrt2 * cross(v1,v2)[m,c]
                float tx = 0.f, ty = 0.f, tz = 0.f;
                #pragma unroll
                for (int m = 0; m < 16; m++) {
                    const float* v1 = &xs[16 + 3 * m];
                    tx = fmaf(v1[1] * v2z - v1[2] * v2y, wk[m], tx);
                    ty = fmaf(v1[2] * v2x - v1[0] * v2z, wk[m], ty);
                    tz = fmaf(v1[0] * v2y - v1[1] * v2x, wk[m], tz);
                }
                int o = g - 96;
                atomicAdd(&nacc[32 + o * 3 + 0], C_A1I2 * tx);
                atomicAdd(&nacc[32 + o * 3 + 1], C_A1I2 * ty);
                atomicAdd(&nacc[32 + o * 3 + 2], C_A1I2 * tz);
            }
        }
        __syncthreads();   // protect w2_s before next chunk load
    }
}

// ---------------- finalize: mean + residual + gating ----------------
__global__ void finalize_kernel(const float* __restrict__ x_dst,
                                const float* __restrict__ Wr0,
                                const float* __restrict__ Wr1,
                                float* __restrict__ out, int N)
{
    int n = blockIdx.x * blockDim.x + threadIdx.x;
    if (n >= N) return;

    float inv = 1.f / fmaxf(g_cnt[n], 1.f);
    float msg[80];
    #pragma unroll
    for (int j = 0; j < 80; j++) msg[j] = g_acc[n * 80 + j] * inv;

    const float* xd = x_dst + n * 64;

    // res0 = sd @ Wr0 / 4
    #pragma unroll 4
    for (int o = 0; o < 32; o++) {
        float t = 0.f;
        #pragma unroll
        for (int m = 0; m < 16; m++) t = fmaf(xd[m], __ldg(&Wr0[m * 32 + o]), t);
        msg[o] += 0.25f * t;
    }
    // res1[o,c] = sum_m vd[m,c]*Wr1[m,o] / 4
    #pragma unroll 4
    for (int o = 0; o < 16; o++) {
        float tx = 0.f, ty = 0.f, tz = 0.f;
        #pragma unroll
        for (int m = 0; m < 16; m++) {
            float w = __ldg(&Wr1[m * 16 + o]);
            const float* vd = &xd[16 + 3 * m];
            tx = fmaf(vd[0], w, tx);
            ty = fmaf(vd[1], w, ty);
            tz = fmaf(vd[2], w, tz);
        }
        msg[32 + o * 3 + 0] += 0.25f * tx;
        msg[32 + o * 3 + 1] += 0.25f * ty;
        msg[32 + o * 3 + 2] += 0.25f * tz;
    }

    float* op = out + n * 64;
    #pragma unroll
    for (int j = 0; j < 16; j++) op[j] = fmaxf(msg[j], 0.f);
    #pragma unroll
    for (int o = 0; o < 16; o++) {
        float gt = 1.f / (1.f + expf(-msg[16 + o]));
        op[16 + o * 3 + 0] = msg[32 + o * 3 + 0] * gt;
        op[16 + o * 3 + 1] = msg[32 + o * 3 + 1] * gt;
        op[16 + o * 3 + 2] = msg[32 + o * 3 + 2] * gt;
    }
}

// ---------------- launch ----------------
extern "C" void kernel_launch(void* const* d_in, const int* in_sizes, int n_in,
                              void* d_out, int out_size)
{
    const int*   dst       = (const int*)  d_in[0];
    const float* x_src     = (const float*)d_in[1];
    const float* x_dst     = (const float*)d_in[2];
    const float* sh        = (const float*)d_in[3];
    const float* edge_attr = (const float*)d_in[4];
    const float* We1       = (const float*)d_in[5];
    const float* be1       = (const float*)d_in[6];
    const float* We2       = (const float*)d_in[7];
    const float* be2       = (const float*)d_in[8];
    const float* Wr0       = (const float*)d_in[9];
    const float* Wr1       = (const float*)d_in[10];
    float* out = (float*)d_out;

    int E = in_sizes[0];
    int N = in_sizes[2] / 64;

    static int smem_set = 0;
    size_t smem_bytes = 20864 * sizeof(float);   // 83,456 B
    cudaFuncSetAttribute(conv_main_kernel,
                         cudaFuncAttributeMaxDynamicSharedMemorySize,
                         (int)smem_bytes);
    (void)smem_set;

    zero_acc_kernel<<<(10000 * 80 + 255) / 256, 256>>>();
    prep_kernel<<<(NGROUPS * 128 * 16 + 255) / 256, 256>>>(We2, be2);
    int nb = (E + TE - 1) / TE;
    conv_main_kernel<<<nb, NTHREADS, smem_bytes>>>(dst, x_src, sh, edge_attr, We1, be1, E);
    finalize_kernel<<<(N + 127) / 128, 128>>>(x_dst, Wr0, Wr1, out, N);
}

// round 4
// speedup vs baseline: 2.9327x; 2.9327x over previous
#include <cuda_runtime.h>
#include <cuda_bf16.h>
#include <cstdint>
#include <math.h>

#define TE        128
#define NTHREADS  256
#define NCHUNK    28       // 1792 cols / 64 per chunk

#define C_A0      0.17677669529663687f   // 1/sqrt(2*16)
#define C_A0I3    0.10206207261596575f   // A0/sqrt(3)
#define C_A1      0.14433756729740643f   // 1/sqrt(3*16)
#define C_A1I2    0.10206207261596577f   // A1/sqrt(2)

// ---------------- smem byte offsets ----------------
#define OFF_A_HI  0                       // A hi: 128 x 136 bf16 = 34816 B
#define OFF_A_LO  34816                   // A lo: 34816 B
#define OFF_B0    69632                   // B buf0: hi 17408 + lo 17408 = 34816 B
#define OFF_B1    104448                  // B buf1: 34816 B
#define OFF_W     139264                  // w staging: 64 x 132 f32 = 33792 B
#define OFF_XS    173056                  // 128 x 69 f32 = 35328 B
#define OFF_BE2   208384                  // 1792 f32 = 7168 B
#define OFF_DST   215552                  // 128 int = 512 B
#define SMEM_TOT  216064
// phase-0 overlay inside the B-buffer region:
#define OFF_EA    69632                   // 128 x 33 f32 = 16896 B
#define OFF_WE1   86528                   // 4096 f32 = 16384 B
#define OFF_BE1   102912                  // 128 f32

// ---------------- device scratch ----------------
__device__ float         g_acc[10000 * 80];
__device__ float         g_cnt[10000];
__device__ __nv_bfloat16 g_W2b[NCHUNK * 17408];   // per chunk: hi[64*136] | lo[64*136]

// ---------------- helpers ----------------
__device__ __forceinline__ uint32_t smem_u32(const void* p) {
    uint32_t a;
    asm("{ .reg .u64 t; cvta.to.shared.u64 t, %1; cvt.u32.u64 %0, t; }" : "=r"(a) : "l"(p));
    return a;
}
#define CP_ASYNC16(d, s)  asm volatile("cp.async.cg.shared.global [%0], [%1], 16;" :: "r"(d), "l"(s) : "memory")
#define CP_COMMIT()       asm volatile("cp.async.commit_group;" ::: "memory")

#define MMA16816(d, a0,a1,a2,a3, b0,b1)                                   \
    asm volatile("mma.sync.aligned.m16n8k16.row.col.f32.bf16.bf16.f32 "  \
        "{%0,%1,%2,%3}, {%4,%5,%6,%7}, {%8,%9}, {%0,%1,%2,%3};"          \
        : "+f"((d)[0]), "+f"((d)[1]), "+f"((d)[2]), "+f"((d)[3])         \
        : "r"(a0), "r"(a1), "r"(a2), "r"(a3), "r"(b0), "r"(b1))

__device__ __forceinline__ uint32_t pack_bf(float s0, float s1) {
    __nv_bfloat16 a = __float2bfloat16(s0), b = __float2bfloat16(s1);
    uint16_t ua = *(uint16_t*)&a, ub = *(uint16_t*)&b;
    return (uint32_t)ua | ((uint32_t)ub << 16);
}

// ---------------- column reorder map (verified round 1) ----------------
__device__ __forceinline__ int orig_k(int g, int m) {
    if (g < 32)  return         m * 32 + g;
    if (g < 64)  return  512 +  m * 32 + (g - 32);
    if (g < 80)  return 1024 +  m * 16 + (g - 64);
    if (g < 96)  return 1280 +  m * 16 + (g - 80);
    return              1536 +  m * 16 + (g - 96);
}

// ---------------- zero ----------------
__global__ void zero_acc_kernel() {
    int idx = blockIdx.x * blockDim.x + threadIdx.x;
    if (idx < 10000 * 80) g_acc[idx] = 0.f;
    if (idx < 10000)      g_cnt[idx] = 0.f;
}

// ---------------- prep: We2 -> bf16 hi/lo chunk blobs [n=64][k=136] ----------------
__global__ void prep_kernel(const float* __restrict__ We2) {
    int idx = blockIdx.x * blockDim.x + threadIdx.x;
    if (idx >= NCHUNK * 8704) return;
    int c = idx / 8704;
    int r = idx - c * 8704;
    int n = r / 136;
    int k = r - n * 136;
    __nv_bfloat16 hi, lo;
    if (k < 128) {
        int col = c * 64 + n;
        float v = We2[k * 1792 + orig_k(col >> 4, col & 15)];
        hi = __float2bfloat16(v);
        lo = __float2bfloat16(v - __bfloat162float(hi));
    } else {
        hi = __float2bfloat16(0.f);
        lo = hi;
    }
    g_W2b[c * 17408 + r]        = hi;
    g_W2b[c * 17408 + 8704 + r] = lo;
}

// ---------------- equivariant contraction -> atomics ----------------
__device__ __forceinline__ void contract_atomic(
    int g, const float* wv, const float* xs,
    float s2, float v2x, float v2y, float v2z, float* nacc)
{
    if (g < 32) {                        // ss
        float t = 0.f;
        #pragma unroll
        for (int m = 0; m < 16; m++) t = fmaf(xs[m], wv[m], t);
        atomicAdd(&nacc[g], C_A0 * s2 * t);
    } else if (g < 64) {                 // vv0
        float t = 0.f;
        #pragma unroll
        for (int m = 0; m < 16; m++) {
            const float* v1 = &xs[16 + 3 * m];
            t = fmaf(v1[0] * v2x + v1[1] * v2y + v1[2] * v2z, wv[m], t);
        }
        atomicAdd(&nacc[g - 32], C_A0I3 * t);
    } else if (g < 80) {                 // sv
        float t = 0.f;
        #pragma unroll
        for (int m = 0; m < 16; m++) t = fmaf(xs[m], wv[m], t);
        float a = C_A1 * t;
        int o = g - 64;
        atomicAdd(&nacc[32 + 3 * o + 0], a * v2x);
        atomicAdd(&nacc[32 + 3 * o + 1], a * v2y);
        atomicAdd(&nacc[32 + 3 * o + 2], a * v2z);
    } else if (g < 96) {                 // vs
        float tx = 0.f, ty = 0.f, tz = 0.f;
        #pragma unroll
        for (int m = 0; m < 16; m++) {
            const float* v1 = &xs[16 + 3 * m];
            tx = fmaf(v1[0], wv[m], tx);
            ty = fmaf(v1[1], wv[m], ty);
            tz = fmaf(v1[2], wv[m], tz);
        }
        float a = C_A1 * s2;
        int o = g - 80;
        atomicAdd(&nacc[32 + 3 * o + 0], a * tx);
        atomicAdd(&nacc[32 + 3 * o + 1], a * ty);
        atomicAdd(&nacc[32 + 3 * o + 2], a * tz);
    } else {                             // vv1 (cross)
        float tx = 0.f, ty = 0.f, tz = 0.f;
        #pragma unroll
        for (int m = 0; m < 16; m++) {
            const float* v1 = &xs[16 + 3 * m];
            tx = fmaf(v1[1] * v2z - v1[2] * v2y, wv[m], tx);
            ty = fmaf(v1[2] * v2x - v1[0] * v2z, wv[m], ty);
            tz = fmaf(v1[0] * v2y - v1[1] * v2x, wv[m], tz);
        }
        int o = g - 96;
        atomicAdd(&nacc[32 + 3 * o + 0], C_A1I2 * tx);
        atomicAdd(&nacc[32 + 3 * o + 1], C_A1I2 * ty);
        atomicAdd(&nacc[32 + 3 * o + 2], C_A1I2 * tz);
    }
}

// ---------------- fused main kernel ----------------
__global__ __launch_bounds__(NTHREADS, 1)
void conv_main_kernel(const int*   __restrict__ dst,
                      const float* __restrict__ x_src,
                      const float* __restrict__ sh,
                      const float* __restrict__ edge_attr,
                      const float* __restrict__ We1,
                      const float* __restrict__ be1,
                      const float* __restrict__ be2,
                      int E)
{
    extern __shared__ char smem[];
    const uint32_t sbase = smem_u32(smem);
    const int tid  = threadIdx.x;
    const int wid  = tid >> 5, lane = tid & 31;
    const int qr   = lane >> 2, qc = lane & 3;
    const int e0   = blockIdx.x * TE;

    float* xs_s  = (float*)(smem + OFF_XS);
    float* be2_s = (float*)(smem + OFF_BE2);
    int*   dst_s = (int*)  (smem + OFF_DST);
    float* ea_s  = (float*)(smem + OFF_EA);
    float* We1_s = (float*)(smem + OFF_WE1);
    float* be1_s = (float*)(smem + OFF_BE1);
    float* w_s   = (float*)(smem + OFF_W);

    // ---- phase 0: loads ----
    for (int idx = tid; idx < 128 * 32; idx += NTHREADS) {
        int e = idx >> 5, d = idx & 31;
        int eg = e0 + e;
        ea_s[e * 33 + d] = (eg < E) ? edge_attr[eg * 32 + d] : 0.f;
    }
    for (int idx = tid; idx < 4096; idx += NTHREADS) We1_s[idx] = We1[idx];
    if (tid < 128) be1_s[tid] = be1[tid];
    for (int idx = tid; idx < 128 * 64; idx += NTHREADS) {
        int e = idx >> 6, j = idx & 63;
        int eg = e0 + e;
        xs_s[e * 69 + j] = (eg < E) ? x_src[eg * 64 + j] : 0.f;
    }
    for (int idx = tid; idx < 128 * 4; idx += NTHREADS) {
        int e = idx >> 2, j = idx & 3;
        int eg = e0 + e;
        xs_s[e * 69 + 64 + j] = (eg < E) ? sh[eg * 4 + j] : 0.f;
    }
    for (int idx = tid; idx < 1792; idx += NTHREADS)
        be2_s[idx] = be2[orig_k(idx >> 4, idx & 15)];
    if (tid < 128) {
        int eg = e0 + tid;
        int dv = (eg < E) ? dst[eg] : 0;
        dst_s[tid] = dv;
        if (eg < E) atomicAdd(&g_cnt[dv], 1.f);
    }
    __syncthreads();

    // ---- H = relu(ea@We1+be1) -> A_hi/A_lo (bf16, [e][k] stride 136) ----
    for (int i = 0; i < 16; i++) {
        int q  = tid + NTHREADS * i;         // 0..4095
        int e  = q & 127;
        int h0 = (q >> 7) * 4;               // 0,4,...,124
        const float* ea = &ea_s[e * 33];
        float s0 = be1_s[h0], s1 = be1_s[h0 + 1];
        float s2 = be1_s[h0 + 2], s3 = be1_s[h0 + 3];
        #pragma unroll
        for (int d = 0; d < 32; d++) {
            float a = ea[d];
            float4 w = *(const float4*)&We1_s[d * 128 + h0];
            s0 = fmaf(a, w.x, s0); s1 = fmaf(a, w.y, s1);
            s2 = fmaf(a, w.z, s2); s3 = fmaf(a, w.w, s3);
        }
        s0 = fmaxf(s0, 0.f); s1 = fmaxf(s1, 0.f);
        s2 = fmaxf(s2, 0.f); s3 = fmaxf(s3, 0.f);
        float h0f = __bfloat162float(__float2bfloat16(s0));
        float h1f = __bfloat162float(__float2bfloat16(s1));
        float h2f = __bfloat162float(__float2bfloat16(s2));
        float h3f = __bfloat162float(__float2bfloat16(s3));
        uint32_t boff = (uint32_t)(e * 136 + h0) * 2u;
        *(uint32_t*)(smem + OFF_A_HI + boff)     = pack_bf(s0, s1);
        *(uint32_t*)(smem + OFF_A_HI + boff + 4) = pack_bf(s2, s3);
        *(uint32_t*)(smem + OFF_A_LO + boff)     = pack_bf(s0 - h0f, s1 - h1f);
        *(uint32_t*)(smem + OFF_A_LO + boff + 4) = pack_bf(s2 - h2f, s3 - h3f);
    }
    __syncthreads();

    // ---- prefetch B chunks 0 and 1 ----
    {
        const char* s0p = (const char*)g_W2b;
        for (int i = tid; i < 2176; i += NTHREADS)
            CP_ASYNC16(sbase + OFF_B0 + i * 16, s0p + i * 16);
        CP_COMMIT();
        const char* s1p = (const char*)g_W2b + 34816;
        for (int i = tid; i < 2176; i += NTHREADS)
            CP_ASYNC16(sbase + OFF_B1 + i * 16, s1p + i * 16);
        CP_COMMIT();
    }

    // ---- per-thread epilogue context ----
    const int  ee    = tid & 127;
    const bool valid = (e0 + ee < E);
    const float* xs  = &xs_s[ee * 69];
    const float es2  = xs[64];
    const float v2x  = xs[65], v2y = xs[66], v2z = xs[67];
    float* nacc = &g_acc[dst_s[ee] * 80];
    const int glsel = (tid >> 7) * 2;       // 0 or 2

    // ---- MMA fragment base offsets ----
    const uint32_t aoff = (uint32_t)((wid * 16 + qr) * 136 + qc * 2) * 2u;
    const char* ah = smem + OFF_A_HI + aoff;
    const char* al = smem + OFF_A_LO + aoff;
    const uint32_t bq = (uint32_t)(qr * 272 + qc * 4);
    const int er = wid * 16 + qr;

    // ---- mainloop ----
    for (int c = 0; c < NCHUNK; c++) {
        if (c < NCHUNK - 1) asm volatile("cp.async.wait_group 1;" ::: "memory");
        else                asm volatile("cp.async.wait_group 0;" ::: "memory");
        __syncthreads();   // B(c) visible; prev epilogue's w_s reads done

        const uint32_t bufo = (c & 1) ? OFF_B1 : OFF_B0;
        const char* bh = smem + bufo + bq;
        const char* bl = smem + bufo + 17408 + bq;

        float acc[8][4];
        #pragma unroll
        for (int nt = 0; nt < 8; nt++) {
            acc[nt][0] = 0.f; acc[nt][1] = 0.f;
            acc[nt][2] = 0.f; acc[nt][3] = 0.f;
        }

        #pragma unroll
        for (int ks = 0; ks < 8; ks++) {
            uint32_t a0 = *(const uint32_t*)(ah + ks * 32);
            uint32_t a1 = *(const uint32_t*)(ah + ks * 32 + 2176);
            uint32_t a2 = *(const uint32_t*)(ah + ks * 32 + 16);
            uint32_t a3 = *(const uint32_t*)(ah + ks * 32 + 2192);
            uint32_t l0 = *(const uint32_t*)(al + ks * 32);
            uint32_t l1 = *(const uint32_t*)(al + ks * 32 + 2176);
            uint32_t l2 = *(const uint32_t*)(al + ks * 32 + 16);
            uint32_t l3 = *(const uint32_t*)(al + ks * 32 + 2192);
            #pragma unroll
            for (int nt = 0; nt < 8; nt++) {
                uint32_t b0 = *(const uint32_t*)(bh + nt * 2176 + ks * 32);
                uint32_t b1 = *(const uint32_t*)(bh + nt * 2176 + ks * 32 + 16);
                uint32_t c0 = *(const uint32_t*)(bl + nt * 2176 + ks * 32);
                uint32_t c1 = *(const uint32_t*)(bl + nt * 2176 + ks * 32 + 16);
                MMA16816(acc[nt], a0, a1, a2, a3, b0, b1);
                MMA16816(acc[nt], l0, l1, l2, l3, b0, b1);
                MMA16816(acc[nt], a0, a1, a2, a3, c0, c1);
            }
        }

        // stage fragments -> w_s [n][e] (stride 132, conflict-free)
        #pragma unroll
        for (int nt = 0; nt < 8; nt++) {
            int n0 = nt * 8 + qc * 2;
            w_s[n0 * 132 + er]           = acc[nt][0];
            w_s[(n0 + 1) * 132 + er]     = acc[nt][1];
            w_s[n0 * 132 + er + 8]       = acc[nt][2];
            w_s[(n0 + 1) * 132 + er + 8] = acc[nt][3];
        }
        __syncthreads();   // w_s complete; MMA reads of buf[c&1] done

        // prefetch chunk c+2 into buf[c&1]
        if (c + 2 < NCHUNK) {
            const char* src = (const char*)g_W2b + (size_t)(c + 2) * 34816;
            for (int i = tid; i < 2176; i += NTHREADS)
                CP_ASYNC16(sbase + bufo + i * 16, src + i * 16);
            CP_COMMIT();
        }

        // epilogue: contract 2 groups per thread, scatter atomics
        if (valid) {
            const int gbase = c * 4 + glsel;
            #pragma unroll
            for (int gi = 0; gi < 2; gi++) {
                int g  = gbase + gi;
                int nl = (glsel + gi) * 16;
                float wv[16];
                const float* bp = &be2_s[g * 16];
                #pragma unroll
                for (int m = 0; m < 16; m++)
                    wv[m] = w_s[(nl + m) * 132 + ee] + bp[m];
                contract_atomic(g, wv, xs, es2, v2x, v2y, v2z, nacc);
            }
        }
        // next iteration's first __syncthreads protects w_s reuse
    }
}

// ---------------- finalize ----------------
__global__ void finalize_kernel(const float* __restrict__ x_dst,
                                const float* __restrict__ Wr0,
                                const float* __restrict__ Wr1,
                                float* __restrict__ out, int N)
{
    int n = blockIdx.x * blockDim.x + threadIdx.x;
    if (n >= N) return;

    float inv = 1.f / fmaxf(g_cnt[n], 1.f);
    float msg[80];
    #pragma unroll
    for (int j = 0; j < 80; j++) msg[j] = g_acc[n * 80 + j] * inv;

    const float* xd = x_dst + n * 64;

    #pragma unroll 4
    for (int o = 0; o < 32; o++) {
        float t = 0.f;
        #pragma unroll
        for (int m = 0; m < 16; m++) t = fmaf(xd[m], __ldg(&Wr0[m * 32 + o]), t);
        msg[o] += 0.25f * t;
    }
    #pragma unroll 4
    for (int o = 0; o < 16; o++) {
        float tx = 0.f, ty = 0.f, tz = 0.f;
        #pragma unroll
        for (int m = 0; m < 16; m++) {
            float w = __ldg(&Wr1[m * 16 + o]);
            const float* vd = &xd[16 + 3 * m];
            tx = fmaf(vd[0], w, tx);
            ty = fmaf(vd[1], w, ty);
            tz = fmaf(vd[2], w, tz);
        }
        msg[32 + o * 3 + 0] += 0.25f * tx;
        msg[32 + o * 3 + 1] += 0.25f * ty;
        msg[32 + o * 3 + 2] += 0.25f * tz;
    }

    float* op = out + n * 64;
    #pragma unroll
    for (int j = 0; j < 16; j++) op[j] = fmaxf(msg[j], 0.f);
    #pragma unroll
    for (int o = 0; o < 16; o++) {
        float gt = 1.f / (1.f + expf(-msg[16 + o]));
        op[16 + o * 3 + 0] = msg[32 + o * 3 + 0] * gt;
        op[16 + o * 3 + 1] = msg[32 + o * 3 + 1] * gt;
        op[16 + o * 3 + 2] = msg[32 + o * 3 + 2] * gt;
    }
}

// ---------------- launch ----------------
extern "C" void kernel_launch(void* const* d_in, const int* in_sizes, int n_in,
                              void* d_out, int out_size)
{
    const int*   dst       = (const int*)  d_in[0];
    const float* x_src     = (const float*)d_in[1];
    const float* x_dst     = (const float*)d_in[2];
    const float* sh        = (const float*)d_in[3];
    const float* edge_attr = (const float*)d_in[4];
    const float* We1       = (const float*)d_in[5];
    const float* be1       = (const float*)d_in[6];
    const float* We2       = (const float*)d_in[7];
    const float* be2       = (const float*)d_in[8];
    const float* Wr0       = (const float*)d_in[9];
    const float* Wr1       = (const float*)d_in[10];
    float* out = (float*)d_out;

    int E = in_sizes[0];
    int N = in_sizes[2] / 64;

    cudaFuncSetAttribute(conv_main_kernel,
                         cudaFuncAttributeMaxDynamicSharedMemorySize, SMEM_TOT);

    zero_acc_kernel<<<(10000 * 80 + 255) / 256, 256>>>();
    prep_kernel<<<(NCHUNK * 8704 + 255) / 256, 256>>>(We2);
    int nb = (E + TE - 1) / TE;
    conv_main_kernel<<<nb, NTHREADS, SMEM_TOT>>>(dst, x_src, sh, edge_attr,
                                                 We1, be1, be2, E);
    finalize_kernel<<<(N + 127) / 128, 128>>>(x_dst, Wr0, Wr1, out, N);
}